// round 2
// baseline (speedup 1.0000x reference)
#include <cuda_runtime.h>
#include <math.h>

#define SQ 4096
#define FD 512

// ---- scratch (allocation-free: __device__ globals) ----
__device__ float g_qq[SQ * FD];
__device__ float g_kk[SQ * FD];
__device__ float g_vv[SQ * FD];
__device__ float g_qk[SQ * FD];
__device__ float g_qv[SQ * FD];
__device__ float g_qatt[SQ];
__device__ float g_den[SQ];
__device__ float g_attn[(size_t)SQ * SQ];   // 64 MB scores / un-normalized exp
__device__ float g_res[SQ * FD];

// ============================================================
// NT SGEMM: C[M,N] = A[M,K](row) * B[N,K](row)^T  (+bias)(relu)
// BM=BN=64, BK=16, 256 threads, 4x4 microtile per thread.
// All dims assumed multiples of 64 / K multiple of 16 (true here).
// ============================================================
template <bool RELU, bool HAS_BIAS>
__global__ void sgemm_nt(const float* __restrict__ A, const float* __restrict__ B,
                         const float* __restrict__ bias, float* __restrict__ C,
                         int M, int N, int K) {
    __shared__ float As[16][64];
    __shared__ float Bs[16][64];
    const int tid = threadIdx.x;
    const int tx = tid & 15;          // 0..15 -> 4 cols each
    const int ty = tid >> 4;          // 0..15 -> 4 rows each
    const int m0 = blockIdx.y * 64;
    const int n0 = blockIdx.x * 64;

    // load mapping: 64x16 tile = 1024 floats, 4 per thread as one float4 along K
    const int lr = tid >> 2;          // 0..63
    const int lk = (tid & 3) * 4;     // 0,4,8,12

    float acc[4][4] = {};

    for (int k0 = 0; k0 < K; k0 += 16) {
        float4 a4 = *(const float4*)(A + (size_t)(m0 + lr) * K + k0 + lk);
        float4 b4 = *(const float4*)(B + (size_t)(n0 + lr) * K + k0 + lk);
        As[lk + 0][lr] = a4.x; As[lk + 1][lr] = a4.y;
        As[lk + 2][lr] = a4.z; As[lk + 3][lr] = a4.w;
        Bs[lk + 0][lr] = b4.x; Bs[lk + 1][lr] = b4.y;
        Bs[lk + 2][lr] = b4.z; Bs[lk + 3][lr] = b4.w;
        __syncthreads();
#pragma unroll
        for (int k = 0; k < 16; k++) {
            float4 av = *(const float4*)&As[k][ty * 4];
            float4 bv = *(const float4*)&Bs[k][tx * 4];
            float a[4] = {av.x, av.y, av.z, av.w};
            float b[4] = {bv.x, bv.y, bv.z, bv.w};
#pragma unroll
            for (int i = 0; i < 4; i++)
#pragma unroll
                for (int j = 0; j < 4; j++)
                    acc[i][j] = fmaf(a[i], b[j], acc[i][j]);
        }
        __syncthreads();
    }

#pragma unroll
    for (int i = 0; i < 4; i++) {
        const int m = m0 + ty * 4 + i;
#pragma unroll
        for (int j = 0; j < 4; j++) {
            const int n = n0 + tx * 4 + j;
            float v = acc[i][j];
            if (HAS_BIAS) v += bias[n];
            if (RELU) v = fmaxf(v, 0.0f);
            C[(size_t)m * N + n] = v;
        }
    }
}

// ============================================================
// NN SGEMM for res = (E[S,S] @ vv[S,F]) / den[s]  +  qv * qatt
// A = E row-major (K contiguous), B = vv row-major (N contiguous)
// ============================================================
__global__ void sgemm_nn_res(const float* __restrict__ E, const float* __restrict__ V,
                             const float* __restrict__ qv, const float* __restrict__ qatt,
                             const float* __restrict__ den, float* __restrict__ C) {
    const int M = SQ, N = FD, K = SQ;
    __shared__ float As[16][64];
    __shared__ float Bs[16][64];
    const int tid = threadIdx.x;
    const int tx = tid & 15;
    const int ty = tid >> 4;
    const int m0 = blockIdx.y * 64;
    const int n0 = blockIdx.x * 64;

    // A load: rows 64 x k 16 (K contiguous) — float4 along K
    const int lr = tid >> 2;
    const int lk = (tid & 3) * 4;
    // B load: k rows 16 x n 64 (N contiguous) — float4 along N
    const int bk = tid >> 4;          // 0..15
    const int bn = (tid & 15) * 4;    // 0..60

    float acc[4][4] = {};

    for (int k0 = 0; k0 < K; k0 += 16) {
        float4 a4 = *(const float4*)(E + (size_t)(m0 + lr) * K + k0 + lk);
        As[lk + 0][lr] = a4.x; As[lk + 1][lr] = a4.y;
        As[lk + 2][lr] = a4.z; As[lk + 3][lr] = a4.w;
        float4 b4 = *(const float4*)(V + (size_t)(k0 + bk) * N + n0 + bn);
        *(float4*)&Bs[bk][bn] = b4;
        __syncthreads();
#pragma unroll
        for (int k = 0; k < 16; k++) {
            float4 av = *(const float4*)&As[k][ty * 4];
            float4 bv = *(const float4*)&Bs[k][tx * 4];
            float a[4] = {av.x, av.y, av.z, av.w};
            float b[4] = {bv.x, bv.y, bv.z, bv.w};
#pragma unroll
            for (int i = 0; i < 4; i++)
#pragma unroll
                for (int j = 0; j < 4; j++)
                    acc[i][j] = fmaf(a[i], b[j], acc[i][j]);
        }
        __syncthreads();
    }

#pragma unroll
    for (int i = 0; i < 4; i++) {
        const int m = m0 + ty * 4 + i;
        const float inv_d = 1.0f / den[m];
        const float qa = qatt[m];
#pragma unroll
        for (int j = 0; j < 4; j++) {
            const int n = n0 + tx * 4 + j;
            C[(size_t)m * N + n] = acc[i][j] * inv_d + qv[(size_t)m * N + n] * qa;
        }
    }
}

// ============================================================
// q_att[s] = sum_f qq[s,f] * qk[s,f]   (one warp per row)
// ============================================================
__global__ void qatt_kernel(const float* __restrict__ qq, const float* __restrict__ qk,
                            float* __restrict__ qatt) {
    const int warp = (blockIdx.x * blockDim.x + threadIdx.x) >> 5;
    const int lane = threadIdx.x & 31;
    if (warp >= SQ) return;
    const float* a = qq + (size_t)warp * FD;
    const float* b = qk + (size_t)warp * FD;
    float sum = 0.0f;
#pragma unroll 4
    for (int i = lane; i < FD; i += 32) sum = fmaf(a[i], b[i], sum);
#pragma unroll
    for (int o = 16; o; o >>= 1) sum += __shfl_xor_sync(0xffffffffu, sum, o);
    if (lane == 0) qatt[warp] = sum;
}

// ============================================================
// Row softmax with extra sink logit q_att[s]*inv. Stores UN-normalized
// exp back into the row; per-row denominator (incl. sink term) to den[].
// ============================================================
__global__ void softmax_kernel(float* __restrict__ attn, const float* __restrict__ qatt,
                               float* __restrict__ den) {
    const int s = blockIdx.x;
    const int tid = threadIdx.x;           // 256 threads
    const float inv = rsqrtf(513.0f);
    float* row = attn + (size_t)s * SQ;
    const float sink = qatt[s] * inv;

    __shared__ float sm_max[8];
    __shared__ float sm_sum[8];

    float m = sink;
    for (int i = tid; i < SQ; i += 256) m = fmaxf(m, row[i] * inv);
#pragma unroll
    for (int o = 16; o; o >>= 1) m = fmaxf(m, __shfl_xor_sync(0xffffffffu, m, o));
    if ((tid & 31) == 0) sm_max[tid >> 5] = m;
    __syncthreads();
    m = sm_max[0];
#pragma unroll
    for (int i = 1; i < 8; i++) m = fmaxf(m, sm_max[i]);

    float lsum = (tid == 0) ? __expf(sink - m) : 0.0f;
    for (int i = tid; i < SQ; i += 256) {
        float e = __expf(row[i] * inv - m);
        row[i] = e;
        lsum += e;
    }
#pragma unroll
    for (int o = 16; o; o >>= 1) lsum += __shfl_xor_sync(0xffffffffu, lsum, o);
    if ((tid & 31) == 0) sm_sum[tid >> 5] = lsum;
    __syncthreads();
    if (tid == 0) {
        float t = 0.0f;
#pragma unroll
        for (int i = 0; i < 8; i++) t += sm_sum[i];
        den[s] = t;
    }
}

// ============================================================
extern "C" void kernel_launch(void* const* d_in, const int* in_sizes, int n_in,
                              void* d_out, int out_size) {
    const float* q  = (const float*)d_in[0];
    const float* k  = (const float*)d_in[1];
    const float* v  = (const float*)d_in[2];
    const float* Wq = (const float*)d_in[3];
    const float* bq = (const float*)d_in[4];
    const float* Wk = (const float*)d_in[5];
    const float* bk = (const float*)d_in[6];
    const float* Wv = (const float*)d_in[7];
    const float* bv = (const float*)d_in[8];
    const float* Wo = (const float*)d_in[9];
    const float* bo = (const float*)d_in[10];
    float* out = (float*)d_out;

    float *qq, *kk, *vv, *qk, *qv, *qatt, *den, *attn, *res;
    cudaGetSymbolAddress((void**)&qq,   g_qq);
    cudaGetSymbolAddress((void**)&kk,   g_kk);
    cudaGetSymbolAddress((void**)&vv,   g_vv);
    cudaGetSymbolAddress((void**)&qk,   g_qk);
    cudaGetSymbolAddress((void**)&qv,   g_qv);
    cudaGetSymbolAddress((void**)&qatt, g_qatt);
    cudaGetSymbolAddress((void**)&den,  g_den);
    cudaGetSymbolAddress((void**)&attn, g_attn);
    cudaGetSymbolAddress((void**)&res,  g_res);

    const dim3 tb(256);
    const dim3 gproj(FD / 64, SQ / 64);     // projections: N=F
    const dim3 gscore(SQ / 64, SQ / 64);    // scores: N=S

    // projections
    sgemm_nt<true,  true><<<gproj, tb>>>(q, Wq, bq, qq, SQ, FD, FD);
    sgemm_nt<true,  true><<<gproj, tb>>>(k, Wk, bk, kk, SQ, FD, FD);
    sgemm_nt<true,  true><<<gproj, tb>>>(v, Wv, bv, vv, SQ, FD, FD);
    sgemm_nt<false, true><<<gproj, tb>>>(q, Wk, bk, qk, SQ, FD, FD);
    sgemm_nt<false, true><<<gproj, tb>>>(q, Wv, bv, qv, SQ, FD, FD);

    // q_att diag term
    qatt_kernel<<<SQ / 8, 256>>>(qq, qk, qatt);

    // scores = qq @ kk^T  (raw, scaling folded into softmax)
    sgemm_nt<false, false><<<gscore, tb>>>(qq, kk, nullptr, attn, SQ, SQ, FD);

    // softmax with sink logit; stores un-normalized exp + per-row denom
    softmax_kernel<<<SQ, 256>>>(attn, qatt, den);

    // res = attn @ vv / den + qv * qatt
    sgemm_nn_res<<<dim3(FD / 64, SQ / 64), tb>>>(attn, vv, qv, qatt, den, res);

    // y = relu(res @ Wo^T + bo)
    sgemm_nt<true, true><<<gproj, tb>>>(res, Wo, bo, out, SQ, FD, FD);
}

// round 6
// speedup vs baseline: 3.7988x; 3.7988x over previous
#include <cuda_runtime.h>
#include <cuda_bf16.h>
#include <math.h>
#include <cstdint>

#define SQ 4096
#define FD 512

// ---- scratch (allocation-free: __device__ globals) ----
__device__ float g_qq[SQ * FD];
__device__ float g_kk[SQ * FD];
__device__ float g_vv[SQ * FD];
__device__ float g_qk[SQ * FD];
__device__ float g_qv[SQ * FD];
__device__ float g_res[SQ * FD];
__device__ float g_qatt[SQ];
__device__ float g_den[SQ];
__device__ float g_scores[(size_t)SQ * SQ];          // fp32 raw scores (64MB)
__device__ __nv_bfloat16 g_ebf[(size_t)SQ * SQ];     // bf16 un-normalized exp (32MB)
__device__ __nv_bfloat16 g_qqb[SQ * FD];
__device__ __nv_bfloat16 g_kkb[SQ * FD];
__device__ __nv_bfloat16 g_vvT[FD * SQ];             // vv transposed, K-major

// ================= helpers =================
__device__ __forceinline__ uint32_t smem_u32(const void* p) {
    uint32_t a;
    asm("{ .reg .u64 t; cvta.to.shared.u64 t, %1; cvt.u32.u64 %0, t; }" : "=r"(a) : "l"(p));
    return a;
}
__device__ __forceinline__ void ldsm4(uint32_t* r, uint32_t a) {
    asm volatile("ldmatrix.sync.aligned.m8n8.x4.shared.b16 {%0,%1,%2,%3}, [%4];"
                 : "=r"(r[0]), "=r"(r[1]), "=r"(r[2]), "=r"(r[3]) : "r"(a));
}
__device__ __forceinline__ void mma16816(float* c, const uint32_t* a, uint32_t b0, uint32_t b1) {
    asm volatile("mma.sync.aligned.m16n8k16.row.col.f32.bf16.bf16.f32 "
                 "{%0,%1,%2,%3}, {%4,%5,%6,%7}, {%8,%9}, {%0,%1,%2,%3};"
                 : "+f"(c[0]), "+f"(c[1]), "+f"(c[2]), "+f"(c[3])
                 : "r"(a[0]), "r"(a[1]), "r"(a[2]), "r"(a[3]), "r"(b0), "r"(b1));
}
__device__ __forceinline__ void mma1688(float* c, const uint32_t* a, uint32_t b0, uint32_t b1) {
    asm volatile("mma.sync.aligned.m16n8k8.row.col.f32.tf32.tf32.f32 "
                 "{%0,%1,%2,%3}, {%4,%5,%6,%7}, {%8,%9}, {%0,%1,%2,%3};"
                 : "+f"(c[0]), "+f"(c[1]), "+f"(c[2]), "+f"(c[3])
                 : "r"(a[0]), "r"(a[1]), "r"(a[2]), "r"(a[3]), "r"(b0), "r"(b1));
}
__device__ __forceinline__ uint32_t f2tf(float f) {
    uint32_t r;
    asm("cvt.rna.tf32.f32 %0, %1;" : "=r"(r) : "f"(f));
    return r;
}

// ============================================================
// bf16 NT GEMM via mma.sync m16n8k16:
//   C[M,*] = A[M,K](row,K-contig) @ B[N,K](row,K-contig)^T
// BM=128, BN=64, BK=32, 256 threads (8 warps, 4m x 2n, warp tile 32x32).
// EPI 0: store fp32.  EPI 1: C = acc/den[r] + qv*qatt (res epilogue).
// ============================================================
template <int EPI>
__global__ void __launch_bounds__(256)
bf16_gemm_nt(const __nv_bfloat16* __restrict__ A, const __nv_bfloat16* __restrict__ B,
             float* __restrict__ C, int K, int ldc,
             const float* __restrict__ qv, const float* __restrict__ qatt,
             const float* __restrict__ den) {
    constexpr int SAS = 40;  // bf16 elems per smem row (32 data + 8 pad) -> 80B stride
    __shared__ __nv_bfloat16 sA[128 * SAS];
    __shared__ __nv_bfloat16 sB[64 * SAS];

    const int tid = threadIdx.x, lane = tid & 31, wid = tid >> 5;
    const int wm = wid & 3, wn = wid >> 2;
    const int m0 = blockIdx.y * 128, n0 = blockIdx.x * 64;

    // global staging: A rows (tid>>2) and (tid>>2)+64, B rows (tid>>2); 16B chunks
    const int ar = tid >> 2;
    const int ac = (tid & 3) * 8;
    const __nv_bfloat16* ag0 = A + (size_t)(m0 + ar) * K + ac;
    const __nv_bfloat16* ag1 = A + (size_t)(m0 + ar + 64) * K + ac;
    const __nv_bfloat16* bg  = B + (size_t)(n0 + ar) * K + ac;
    uint4* sa0 = (uint4*)(sA + ar * SAS + ac);
    uint4* sa1 = (uint4*)(sA + (ar + 64) * SAS + ac);
    uint4* sb0 = (uint4*)(sB + ar * SAS + ac);

    const uint32_t smA = smem_u32(sA), smB = smem_u32(sB);
    const int rowA = lane & 15;
    const int koffA = (lane >> 4) * 8;
    const int noffB = (lane & 7) + ((lane >> 4) << 3);
    const int koffB = ((lane >> 3) & 1) * 8;

    float c[2][4][4] = {};

    uint4 stA0 = *(const uint4*)ag0;
    uint4 stA1 = *(const uint4*)ag1;
    uint4 stB  = *(const uint4*)bg;

    const int nIter = K >> 5;
    for (int it = 0; it < nIter; it++) {
        *sa0 = stA0; *sa1 = stA1; *sb0 = stB;
        __syncthreads();
        if (it + 1 < nIter) {
            const int k0 = (it + 1) << 5;
            stA0 = *(const uint4*)(ag0 + k0);
            stA1 = *(const uint4*)(ag1 + k0);
            stB  = *(const uint4*)(bg + k0);
        }
#pragma unroll
        for (int ks = 0; ks < 2; ks++) {
            uint32_t a[2][4], b[2][4];
#pragma unroll
            for (int fm = 0; fm < 2; fm++)
                ldsm4(a[fm], smA + (uint32_t)(((wm * 32 + fm * 16 + rowA) * SAS + ks * 16 + koffA) * 2));
#pragma unroll
            for (int g = 0; g < 2; g++)
                ldsm4(b[g], smB + (uint32_t)(((wn * 32 + g * 16 + noffB) * SAS + ks * 16 + koffB) * 2));
#pragma unroll
            for (int fm = 0; fm < 2; fm++) {
                mma16816(c[fm][0], a[fm], b[0][0], b[0][1]);
                mma16816(c[fm][1], a[fm], b[0][2], b[0][3]);
                mma16816(c[fm][2], a[fm], b[1][0], b[1][1]);
                mma16816(c[fm][3], a[fm], b[1][2], b[1][3]);
            }
        }
        __syncthreads();
    }

    // ---- epilogue ----
    const int rbase = m0 + wm * 32 + (lane >> 2);
    const int cbase = n0 + wn * 32 + (lane & 3) * 2;
#pragma unroll
    for (int fm = 0; fm < 2; fm++) {
        const int r = rbase + fm * 16;
        if (EPI == 0) {
#pragma unroll
            for (int j = 0; j < 4; j++) {
                const int cc = cbase + j * 8;
                *(float2*)(C + (size_t)r * ldc + cc) = make_float2(c[fm][j][0], c[fm][j][1]);
                *(float2*)(C + (size_t)(r + 8) * ldc + cc) = make_float2(c[fm][j][2], c[fm][j][3]);
            }
        } else {
            const float i0 = __frcp_rn(den[r]),     qa0 = qatt[r];
            const float i1 = __frcp_rn(den[r + 8]), qa1 = qatt[r + 8];
#pragma unroll
            for (int j = 0; j < 4; j++) {
                const int cc = cbase + j * 8;
                float2 v0 = *(const float2*)(qv + (size_t)r * ldc + cc);
                float2 v1 = *(const float2*)(qv + (size_t)(r + 8) * ldc + cc);
                *(float2*)(C + (size_t)r * ldc + cc) =
                    make_float2(c[fm][j][0] * i0 + v0.x * qa0, c[fm][j][1] * i0 + v0.y * qa0);
                *(float2*)(C + (size_t)(r + 8) * ldc + cc) =
                    make_float2(c[fm][j][2] * i1 + v1.x * qa1, c[fm][j][3] * i1 + v1.y * qa1);
            }
        }
    }
}

// ============================================================
// tf32 NT GEMM via mma.sync m16n8k8 (projections):
//   C = relu?(A@B^T + bias), optional bf16 copy (row / transposed)
// BM=128, BN=64, BK=16, 256 threads (4m x 2n warps, warp tile 32x32).
// ============================================================
template <bool RELU, int BFMODE>
__global__ void __launch_bounds__(256)
tf32_gemm_nt(const float* __restrict__ A, const float* __restrict__ B,
             const float* __restrict__ bias, float* __restrict__ C,
             __nv_bfloat16* __restrict__ Cb, int K, int N) {
    constexpr int SAS = 20;  // fp32 elems per smem row (16 data + 4 pad)
    __shared__ uint32_t sA[128 * SAS];
    __shared__ uint32_t sB[64 * SAS];

    const int tid = threadIdx.x, lane = tid & 31, wid = tid >> 5;
    const int wm = wid & 3, wn = wid >> 2;
    const int m0 = blockIdx.y * 128, n0 = blockIdx.x * 64;

    const int ar = tid >> 2;
    const int ac = (tid & 3) * 4;
    const float* ag0 = A + (size_t)(m0 + ar) * K + ac;
    const float* ag1 = A + (size_t)(m0 + ar + 64) * K + ac;
    const float* bg  = B + (size_t)(n0 + ar) * K + ac;
    uint32_t* sa0 = sA + ar * SAS + ac;
    uint32_t* sa1 = sA + (ar + 64) * SAS + ac;
    uint32_t* sb0 = sB + ar * SAS + ac;

    const int t4 = lane >> 2, c4 = lane & 3;

    float c[2][4][4] = {};

    float4 stA0 = *(const float4*)ag0;
    float4 stA1 = *(const float4*)ag1;
    float4 stB  = *(const float4*)bg;

    const int nIter = K >> 4;
    for (int it = 0; it < nIter; it++) {
        sa0[0] = f2tf(stA0.x); sa0[1] = f2tf(stA0.y); sa0[2] = f2tf(stA0.z); sa0[3] = f2tf(stA0.w);
        sa1[0] = f2tf(stA1.x); sa1[1] = f2tf(stA1.y); sa1[2] = f2tf(stA1.z); sa1[3] = f2tf(stA1.w);
        sb0[0] = f2tf(stB.x);  sb0[1] = f2tf(stB.y);  sb0[2] = f2tf(stB.z);  sb0[3] = f2tf(stB.w);
        __syncthreads();
        if (it + 1 < nIter) {
            const int k0 = (it + 1) << 4;
            stA0 = *(const float4*)(ag0 + k0);
            stA1 = *(const float4*)(ag1 + k0);
            stB  = *(const float4*)(bg + k0);
        }
#pragma unroll
        for (int ks = 0; ks < 2; ks++) {
            uint32_t a[2][4], b[4][2];
#pragma unroll
            for (int fm = 0; fm < 2; fm++) {
                const int rb = (wm * 32 + fm * 16 + t4) * SAS + ks * 8 + c4;
                a[fm][0] = sA[rb];
                a[fm][1] = sA[rb + 8 * SAS];
                a[fm][2] = sA[rb + 4];
                a[fm][3] = sA[rb + 8 * SAS + 4];
            }
#pragma unroll
            for (int nf = 0; nf < 4; nf++) {
                const int nb = (wn * 32 + nf * 8 + t4) * SAS + ks * 8 + c4;
                b[nf][0] = sB[nb];
                b[nf][1] = sB[nb + 4];
            }
#pragma unroll
            for (int fm = 0; fm < 2; fm++)
#pragma unroll
                for (int nf = 0; nf < 4; nf++)
                    mma1688(c[fm][nf], a[fm], b[nf][0], b[nf][1]);
        }
        __syncthreads();
    }

    // ---- epilogue: bias + relu + fp32 store + optional bf16 copies ----
    const int rbase = m0 + wm * 32 + t4;
    const int cbase = n0 + wn * 32 + c4 * 2;
#pragma unroll
    for (int fm = 0; fm < 2; fm++) {
#pragma unroll
        for (int j = 0; j < 4; j++) {
            const int cc = cbase + j * 8;
            const float b0 = bias[cc], b1 = bias[cc + 1];
#pragma unroll
            for (int h = 0; h < 2; h++) {
                const int r = rbase + fm * 16 + h * 8;
                float v0 = c[fm][j][2 * h] + b0;
                float v1 = c[fm][j][2 * h + 1] + b1;
                if (RELU) { v0 = fmaxf(v0, 0.0f); v1 = fmaxf(v1, 0.0f); }
                *(float2*)(C + (size_t)r * N + cc) = make_float2(v0, v1);
                if (BFMODE == 1) {
                    __nv_bfloat162* p = (__nv_bfloat162*)(Cb + (size_t)r * N + cc);
                    *p = __nv_bfloat162(__float2bfloat16(v0), __float2bfloat16(v1));
                }
                if (BFMODE == 2) {
                    Cb[(size_t)cc * SQ + r] = __float2bfloat16(v0);
                    Cb[(size_t)(cc + 1) * SQ + r] = __float2bfloat16(v1);
                }
            }
        }
    }
}

// ============================================================
// q_att[s] = sum_f qq[s,f]*qk[s,f]
// ============================================================
__global__ void qatt_kernel(const float* __restrict__ qq, const float* __restrict__ qk,
                            float* __restrict__ qatt) {
    const int warp = (blockIdx.x * blockDim.x + threadIdx.x) >> 5;
    const int lane = threadIdx.x & 31;
    if (warp >= SQ) return;
    const float* a = qq + (size_t)warp * FD;
    const float* b = qk + (size_t)warp * FD;
    float sum = 0.0f;
#pragma unroll 4
    for (int i = lane; i < FD; i += 32) sum = fmaf(a[i], b[i], sum);
#pragma unroll
    for (int o = 16; o; o >>= 1) sum += __shfl_xor_sync(0xffffffffu, sum, o);
    if (lane == 0) qatt[warp] = sum;
}

// ============================================================
// Row softmax with sink logit; fp32 scores -> bf16 un-normalized exp + fp32 denom
// ============================================================
__global__ void softmax_kernel(const float* __restrict__ scores, __nv_bfloat16* __restrict__ ebf,
                               const float* __restrict__ qatt, float* __restrict__ den) {
    const int s = blockIdx.x;
    const int tid = threadIdx.x;  // 256
    const float inv = rsqrtf(513.0f);
    const float* row = scores + (size_t)s * SQ;
    __nv_bfloat16* erow = ebf + (size_t)s * SQ;
    const float sink = qatt[s] * inv;

    __shared__ float sm_max[8];
    __shared__ float sm_sum[8];

    float m = sink;
    for (int i = tid; i < SQ; i += 256) m = fmaxf(m, row[i] * inv);
#pragma unroll
    for (int o = 16; o; o >>= 1) m = fmaxf(m, __shfl_xor_sync(0xffffffffu, m, o));
    if ((tid & 31) == 0) sm_max[tid >> 5] = m;
    __syncthreads();
    m = sm_max[0];
#pragma unroll
    for (int i = 1; i < 8; i++) m = fmaxf(m, sm_max[i]);

    float lsum = (tid == 0) ? __expf(sink - m) : 0.0f;
    for (int i = tid; i < SQ; i += 256) {
        float e = __expf(row[i] * inv - m);
        erow[i] = __float2bfloat16(e);
        lsum += e;
    }
#pragma unroll
    for (int o = 16; o; o >>= 1) lsum += __shfl_xor_sync(0xffffffffu, lsum, o);
    if ((tid & 31) == 0) sm_sum[tid >> 5] = lsum;
    __syncthreads();
    if (tid == 0) {
        float t = 0.0f;
#pragma unroll
        for (int i = 0; i < 8; i++) t += sm_sum[i];
        den[s] = t;
    }
}

// ============================================================
extern "C" void kernel_launch(void* const* d_in, const int* in_sizes, int n_in,
                              void* d_out, int out_size) {
    const float* q  = (const float*)d_in[0];
    const float* k  = (const float*)d_in[1];
    const float* v  = (const float*)d_in[2];
    const float* Wq = (const float*)d_in[3];
    const float* bq = (const float*)d_in[4];
    const float* Wk = (const float*)d_in[5];
    const float* bk = (const float*)d_in[6];
    const float* Wv = (const float*)d_in[7];
    const float* bv = (const float*)d_in[8];
    const float* Wo = (const float*)d_in[9];
    const float* bo = (const float*)d_in[10];
    float* out = (float*)d_out;

    float *qq, *kk, *vv, *qk, *qv, *qatt, *den, *scores, *res;
    __nv_bfloat16 *qqb, *kkb, *vvT, *ebf;
    cudaGetSymbolAddress((void**)&qq, g_qq);
    cudaGetSymbolAddress((void**)&kk, g_kk);
    cudaGetSymbolAddress((void**)&vv, g_vv);
    cudaGetSymbolAddress((void**)&qk, g_qk);
    cudaGetSymbolAddress((void**)&qv, g_qv);
    cudaGetSymbolAddress((void**)&qatt, g_qatt);
    cudaGetSymbolAddress((void**)&den, g_den);
    cudaGetSymbolAddress((void**)&scores, g_scores);
    cudaGetSymbolAddress((void**)&res, g_res);
    cudaGetSymbolAddress((void**)&qqb, g_qqb);
    cudaGetSymbolAddress((void**)&kkb, g_kkb);
    cudaGetSymbolAddress((void**)&vvT, g_vvT);
    cudaGetSymbolAddress((void**)&ebf, g_ebf);

    const dim3 tproj(FD / 64, SQ / 128);     // (8, 32)

    // projections (tf32 tensor) + free bf16 copies in epilogue
    tf32_gemm_nt<true,  1><<<tproj, 256>>>(q, Wq, bq, qq, qqb, FD, FD);
    tf32_gemm_nt<true,  1><<<tproj, 256>>>(k, Wk, bk, kk, kkb, FD, FD);
    tf32_gemm_nt<true,  2><<<tproj, 256>>>(v, Wv, bv, vv, vvT, FD, FD);
    tf32_gemm_nt<false, 0><<<tproj, 256>>>(q, Wk, bk, qk, nullptr, FD, FD);
    tf32_gemm_nt<false, 0><<<tproj, 256>>>(q, Wv, bv, qv, nullptr, FD, FD);

    // q_att diag term (fp32)
    qatt_kernel<<<SQ / 8, 256>>>(qq, qk, qatt);

    // scores = qq @ kk^T  (bf16 HMMA, fp32 accum)
    bf16_gemm_nt<0><<<dim3(SQ / 64, SQ / 128), 256>>>(
        qqb, kkb, scores, FD, SQ, nullptr, nullptr, nullptr);

    // softmax w/ sink: bf16 un-normalized exp + fp32 denom
    softmax_kernel<<<SQ, 256>>>(scores, ebf, qatt, den);

    // res = (E @ vv)/den + qv*qatt  (bf16 HMMA; E K-major, vvT K-major)
    bf16_gemm_nt<1><<<dim3(FD / 64, SQ / 128), 256>>>(
        ebf, vvT, res, SQ, FD, qv, qatt, den);

    // y = relu(res @ Wo^T + bo)  (tf32 tensor)
    tf32_gemm_nt<true, 0><<<tproj, 256>>>(res, Wo, bo, out, nullptr, FD, FD);
}

// round 7
// speedup vs baseline: 4.7322x; 1.2457x over previous
#include <cuda_runtime.h>
#include <cuda_bf16.h>
#include <math.h>
#include <cstdint>

#define SQ 4096
#define FD 512

// ---- scratch (allocation-free: __device__ globals) ----
__device__ float g_qq[SQ * FD];
__device__ float g_kk[SQ * FD];
__device__ float g_vv[SQ * FD];
__device__ float g_qk[SQ * FD];
__device__ float g_qv[SQ * FD];
__device__ float g_res[SQ * FD];
__device__ float g_qatt[SQ];
__device__ float g_den[SQ];
__device__ float g_scores[(size_t)SQ * SQ];          // fp32 raw scores (64MB)
__device__ __nv_bfloat16 g_ebf[(size_t)SQ * SQ];     // bf16 un-normalized exp (32MB)
__device__ __nv_bfloat16 g_qqb[SQ * FD];
__device__ __nv_bfloat16 g_kkb[SQ * FD];
__device__ __nv_bfloat16 g_vvT[FD * SQ];             // vv transposed, K-major

// ================= helpers =================
__device__ __forceinline__ uint32_t smem_u32(const void* p) {
    uint32_t a;
    asm("{ .reg .u64 t; cvta.to.shared.u64 t, %1; cvt.u32.u64 %0, t; }" : "=r"(a) : "l"(p));
    return a;
}
__device__ __forceinline__ void ldsm4(uint32_t* r, uint32_t a) {
    asm volatile("ldmatrix.sync.aligned.m8n8.x4.shared.b16 {%0,%1,%2,%3}, [%4];"
                 : "=r"(r[0]), "=r"(r[1]), "=r"(r[2]), "=r"(r[3]) : "r"(a));
}
__device__ __forceinline__ void mma16816(float* c, const uint32_t* a, uint32_t b0, uint32_t b1) {
    asm volatile("mma.sync.aligned.m16n8k16.row.col.f32.bf16.bf16.f32 "
                 "{%0,%1,%2,%3}, {%4,%5,%6,%7}, {%8,%9}, {%0,%1,%2,%3};"
                 : "+f"(c[0]), "+f"(c[1]), "+f"(c[2]), "+f"(c[3])
                 : "r"(a[0]), "r"(a[1]), "r"(a[2]), "r"(a[3]), "r"(b0), "r"(b1));
}
__device__ __forceinline__ void mma1688(float* c, const uint32_t* a, uint32_t b0, uint32_t b1) {
    asm volatile("mma.sync.aligned.m16n8k8.row.col.f32.tf32.tf32.f32 "
                 "{%0,%1,%2,%3}, {%4,%5,%6,%7}, {%8,%9}, {%0,%1,%2,%3};"
                 : "+f"(c[0]), "+f"(c[1]), "+f"(c[2]), "+f"(c[3])
                 : "r"(a[0]), "r"(a[1]), "r"(a[2]), "r"(a[3]), "r"(b0), "r"(b1));
}
__device__ __forceinline__ uint32_t f2tf(float f) {
    uint32_t r;
    asm("cvt.rna.tf32.f32 %0, %1;" : "=r"(r) : "f"(f));
    return r;
}
__device__ __forceinline__ void cp16(uint32_t s, const void* g) {
    asm volatile("cp.async.cg.shared.global [%0], [%1], 16;" :: "r"(s), "l"(g));
}
#define CP_COMMIT() asm volatile("cp.async.commit_group;" ::: "memory")
#define CP_WAIT0()  asm volatile("cp.async.wait_group 0;" ::: "memory")

// ============================================================
// bf16 NT GEMM via mma.sync m16n8k16 + cp.async 2-stage pipeline:
//   C[M,*] = A[M,K](row,K-contig) @ B[N,K](row,K-contig)^T
// BM=128, BN=128, BK=32, 256 threads (8 warps: 4m x 2n, warp tile 32x64).
// EPI 0: store fp32.  EPI 1: C = acc/den[r] + qv*qatt (res epilogue).
// ============================================================
template <int EPI>
__global__ void __launch_bounds__(256)
bf16_gemm_nt(const __nv_bfloat16* __restrict__ A, const __nv_bfloat16* __restrict__ B,
             float* __restrict__ C, int K, int ldc,
             const float* __restrict__ qv, const float* __restrict__ qatt,
             const float* __restrict__ den) {
    constexpr int BN = 128, G = BN / 32;   // 4 ldsm groups per ks on B
    constexpr int SAS = 40;                // bf16 per smem row (32 + 8 pad) = 80B
    __shared__ __nv_bfloat16 sA[2][128 * SAS];
    __shared__ __nv_bfloat16 sB[2][BN * SAS];

    const int tid = threadIdx.x, lane = tid & 31, wid = tid >> 5;
    const int wm = wid & 3, wn = wid >> 2;
    const int m0 = blockIdx.y * 128, n0 = blockIdx.x * BN;
    const uint32_t baseA = smem_u32(sA), baseB = smem_u32(sB);

    const int cr = tid >> 2;            // chunk row
    const int cc = (tid & 3) * 8;       // chunk col (bf16 elems), 16B chunks

    const int n = K >> 5;

    // prologue: stage 0 <- chunk 0
    {
        cp16(baseA + cr * 80 + (cc * 2), A + (size_t)(m0 + cr) * K + cc);
        cp16(baseA + (cr + 64) * 80 + (cc * 2), A + (size_t)(m0 + cr + 64) * K + cc);
        cp16(baseB + cr * 80 + (cc * 2), B + (size_t)(n0 + cr) * K + cc);
        cp16(baseB + (cr + 64) * 80 + (cc * 2), B + (size_t)(n0 + cr + 64) * K + cc);
        CP_COMMIT();
    }

    const int rowA = lane & 15, koffA = (lane >> 4) * 8;
    const int noffB = (lane & 7) + ((lane >> 4) << 3), koffB = ((lane >> 3) & 1) * 8;

    float c[2][2 * G][4] = {};

    for (int it = 0; it < n; it++) {
        CP_WAIT0();          // chunk `it` landed (only group `it` outstanding)
        __syncthreads();     // visible to all; all warps done with compute(it-1)
        if (it + 1 < n) {    // stage (it+1)&1 <- chunk it+1 (overlaps compute below)
            const int s = (it + 1) & 1;
            const int k0 = (it + 1) << 5;
            const uint32_t sa = baseA + s * (128 * SAS * 2);
            const uint32_t sb = baseB + s * (BN * SAS * 2);
            cp16(sa + cr * 80 + (cc * 2), A + (size_t)(m0 + cr) * K + k0 + cc);
            cp16(sa + (cr + 64) * 80 + (cc * 2), A + (size_t)(m0 + cr + 64) * K + k0 + cc);
            cp16(sb + cr * 80 + (cc * 2), B + (size_t)(n0 + cr) * K + k0 + cc);
            cp16(sb + (cr + 64) * 80 + (cc * 2), B + (size_t)(n0 + cr + 64) * K + k0 + cc);
            CP_COMMIT();
        }
        const uint32_t smA = baseA + (it & 1) * (128 * SAS * 2);
        const uint32_t smB = baseB + (it & 1) * (BN * SAS * 2);
#pragma unroll
        for (int ks = 0; ks < 2; ks++) {
            uint32_t a[2][4], b[G][4];
#pragma unroll
            for (int fm = 0; fm < 2; fm++)
                ldsm4(a[fm], smA + (uint32_t)(((wm * 32 + fm * 16 + rowA) * SAS + ks * 16 + koffA) * 2));
#pragma unroll
            for (int g = 0; g < G; g++)
                ldsm4(b[g], smB + (uint32_t)(((wn * 64 + g * 16 + noffB) * SAS + ks * 16 + koffB) * 2));
#pragma unroll
            for (int fm = 0; fm < 2; fm++)
#pragma unroll
                for (int g = 0; g < G; g++) {
                    mma16816(c[fm][2 * g], a[fm], b[g][0], b[g][1]);
                    mma16816(c[fm][2 * g + 1], a[fm], b[g][2], b[g][3]);
                }
        }
    }

    // ---- epilogue ----
    const int rbase = m0 + wm * 32 + (lane >> 2);
    const int cbase = n0 + wn * 64 + (lane & 3) * 2;
#pragma unroll
    for (int fm = 0; fm < 2; fm++) {
        const int r = rbase + fm * 16;
        if (EPI == 0) {
#pragma unroll
            for (int j = 0; j < 2 * G; j++) {
                const int col = cbase + j * 8;
                *(float2*)(C + (size_t)r * ldc + col) = make_float2(c[fm][j][0], c[fm][j][1]);
                *(float2*)(C + (size_t)(r + 8) * ldc + col) = make_float2(c[fm][j][2], c[fm][j][3]);
            }
        } else {
            const float i0 = __frcp_rn(den[r]),     qa0 = qatt[r];
            const float i1 = __frcp_rn(den[r + 8]), qa1 = qatt[r + 8];
#pragma unroll
            for (int j = 0; j < 2 * G; j++) {
                const int col = cbase + j * 8;
                float2 v0 = *(const float2*)(qv + (size_t)r * ldc + col);
                float2 v1 = *(const float2*)(qv + (size_t)(r + 8) * ldc + col);
                *(float2*)(C + (size_t)r * ldc + col) =
                    make_float2(c[fm][j][0] * i0 + v0.x * qa0, c[fm][j][1] * i0 + v0.y * qa0);
                *(float2*)(C + (size_t)(r + 8) * ldc + col) =
                    make_float2(c[fm][j][2] * i1 + v1.x * qa1, c[fm][j][3] * i1 + v1.y * qa1);
            }
        }
    }
}

// ============================================================
// tf32 NT GEMM (projections), z-fused: per-z {A,B,bias,C,Cb,relu,bf}
// BM=128, BN=64, BK=16, 256 threads, 2-stage smem, reg-staged loads,
// packed STS.128 tf32 stores, one __syncthreads per K-chunk.
// ============================================================
struct ProjTab {
    const float* A; const float* B; const float* bias;
    float* C; __nv_bfloat16* Cb; int relu; int bf;
};
struct ProjArgs { ProjTab t[5]; };

__global__ void __launch_bounds__(256)
tf32_proj(ProjArgs pa) {
    const ProjTab T = pa.t[blockIdx.z];
    const float* __restrict__ A = T.A;
    const float* __restrict__ B = T.B;
    const int K = FD, N = FD;
    constexpr int SAS = 20;  // fp32 per smem row (16 + 4 pad) = 80B
    __shared__ uint32_t sA[2][128 * SAS];
    __shared__ uint32_t sB[2][64 * SAS];

    const int tid = threadIdx.x, lane = tid & 31, wid = tid >> 5;
    const int wm = wid & 3, wn = wid >> 2;
    const int m0 = blockIdx.y * 128, n0 = blockIdx.x * 64;

    const int ar = tid >> 2;
    const int ac = (tid & 3) * 4;
    const float* ag0 = A + (size_t)(m0 + ar) * K + ac;
    const float* ag1 = A + (size_t)(m0 + ar + 64) * K + ac;
    const float* bg  = B + (size_t)(n0 + ar) * K + ac;

    const int t4 = lane >> 2, c4 = lane & 3;
    float c[2][4][4] = {};

    float4 rA0 = *(const float4*)ag0;
    float4 rA1 = *(const float4*)ag1;
    float4 rB  = *(const float4*)bg;

    const int n = K >> 4;  // 32
    // store chunk 0 into stage 0
    {
        uint4 u;
        u.x = f2tf(rA0.x); u.y = f2tf(rA0.y); u.z = f2tf(rA0.z); u.w = f2tf(rA0.w);
        *(uint4*)&sA[0][ar * SAS + ac] = u;
        u.x = f2tf(rA1.x); u.y = f2tf(rA1.y); u.z = f2tf(rA1.z); u.w = f2tf(rA1.w);
        *(uint4*)&sA[0][(ar + 64) * SAS + ac] = u;
        u.x = f2tf(rB.x); u.y = f2tf(rB.y); u.z = f2tf(rB.z); u.w = f2tf(rB.w);
        *(uint4*)&sB[0][ar * SAS + ac] = u;
    }
    __syncthreads();

    for (int it = 0; it < n; it++) {
        if (it + 1 < n) {
            const int k0 = (it + 1) << 4;
            rA0 = *(const float4*)(ag0 + k0);
            rA1 = *(const float4*)(ag1 + k0);
            rB  = *(const float4*)(bg + k0);
        }
        const uint32_t* cA = sA[it & 1];
        const uint32_t* cB = sB[it & 1];
#pragma unroll
        for (int ks = 0; ks < 2; ks++) {
            uint32_t a[2][4], b[4][2];
#pragma unroll
            for (int fm = 0; fm < 2; fm++) {
                const int rb = (wm * 32 + fm * 16 + t4) * SAS + ks * 8 + c4;
                a[fm][0] = cA[rb];
                a[fm][1] = cA[rb + 8 * SAS];
                a[fm][2] = cA[rb + 4];
                a[fm][3] = cA[rb + 8 * SAS + 4];
            }
#pragma unroll
            for (int nf = 0; nf < 4; nf++) {
                const int nb = (wn * 32 + nf * 8 + t4) * SAS + ks * 8 + c4;
                b[nf][0] = cB[nb];
                b[nf][1] = cB[nb + 4];
            }
#pragma unroll
            for (int fm = 0; fm < 2; fm++)
#pragma unroll
                for (int nf = 0; nf < 4; nf++)
                    mma1688(c[fm][nf], a[fm], b[nf][0], b[nf][1]);
        }
        if (it + 1 < n) {
            const int s = (it + 1) & 1;
            uint4 u;
            u.x = f2tf(rA0.x); u.y = f2tf(rA0.y); u.z = f2tf(rA0.z); u.w = f2tf(rA0.w);
            *(uint4*)&sA[s][ar * SAS + ac] = u;
            u.x = f2tf(rA1.x); u.y = f2tf(rA1.y); u.z = f2tf(rA1.z); u.w = f2tf(rA1.w);
            *(uint4*)&sA[s][(ar + 64) * SAS + ac] = u;
            u.x = f2tf(rB.x); u.y = f2tf(rB.y); u.z = f2tf(rB.z); u.w = f2tf(rB.w);
            *(uint4*)&sB[s][ar * SAS + ac] = u;
            __syncthreads();
        }
    }

    // ---- epilogue ----
    const int rbase = m0 + wm * 32 + t4;
    const int cbase = n0 + wn * 32 + c4 * 2;
    const int relu = T.relu, bf = T.bf;
    float* C = T.C;
    __nv_bfloat16* Cb = T.Cb;
#pragma unroll
    for (int fm = 0; fm < 2; fm++) {
#pragma unroll
        for (int j = 0; j < 4; j++) {
            const int col = cbase + j * 8;
            const float b0 = T.bias[col], b1 = T.bias[col + 1];
#pragma unroll
            for (int h = 0; h < 2; h++) {
                const int r = rbase + fm * 16 + h * 8;
                float v0 = c[fm][j][2 * h] + b0;
                float v1 = c[fm][j][2 * h + 1] + b1;
                if (relu) { v0 = fmaxf(v0, 0.0f); v1 = fmaxf(v1, 0.0f); }
                *(float2*)(C + (size_t)r * N + col) = make_float2(v0, v1);
                if (bf == 1) {
                    *(__nv_bfloat162*)(Cb + (size_t)r * N + col) =
                        __nv_bfloat162(__float2bfloat16(v0), __float2bfloat16(v1));
                } else if (bf == 2) {
                    Cb[(size_t)col * SQ + r] = __float2bfloat16(v0);
                    Cb[(size_t)(col + 1) * SQ + r] = __float2bfloat16(v1);
                }
            }
        }
    }
}

// ============================================================
// q_att[s] = sum_f qq[s,f]*qk[s,f]
// ============================================================
__global__ void qatt_kernel(const float* __restrict__ qq, const float* __restrict__ qk,
                            float* __restrict__ qatt) {
    const int warp = (blockIdx.x * blockDim.x + threadIdx.x) >> 5;
    const int lane = threadIdx.x & 31;
    if (warp >= SQ) return;
    const float4* a = (const float4*)(qq + (size_t)warp * FD);
    const float4* b = (const float4*)(qk + (size_t)warp * FD);
    float sum = 0.0f;
#pragma unroll
    for (int i = lane; i < FD / 4; i += 32) {
        float4 x = a[i], y = b[i];
        sum = fmaf(x.x, y.x, sum); sum = fmaf(x.y, y.y, sum);
        sum = fmaf(x.z, y.z, sum); sum = fmaf(x.w, y.w, sum);
    }
#pragma unroll
    for (int o = 16; o; o >>= 1) sum += __shfl_xor_sync(0xffffffffu, sum, o);
    if (lane == 0) qatt[warp] = sum;
}

// ============================================================
// Row softmax with sink logit; fp32 scores -> bf16 un-normalized exp + fp32 denom
// ============================================================
__global__ void softmax_kernel(const float* __restrict__ scores, __nv_bfloat16* __restrict__ ebf,
                               const float* __restrict__ qatt, float* __restrict__ den) {
    const int s = blockIdx.x;
    const int tid = threadIdx.x;  // 256
    const float inv = rsqrtf(513.0f);
    const float4* row4 = (const float4*)(scores + (size_t)s * SQ);
    __nv_bfloat162* erow2 = (__nv_bfloat162*)(ebf + (size_t)s * SQ);
    const float sink = qatt[s] * inv;

    __shared__ float sm_max[8];
    __shared__ float sm_sum[8];

    float m = sink;
#pragma unroll
    for (int i = tid; i < SQ / 4; i += 256) {
        float4 v = row4[i];
        m = fmaxf(m, fmaxf(fmaxf(v.x, v.y), fmaxf(v.z, v.w)) * inv);
    }
#pragma unroll
    for (int o = 16; o; o >>= 1) m = fmaxf(m, __shfl_xor_sync(0xffffffffu, m, o));
    if ((tid & 31) == 0) sm_max[tid >> 5] = m;
    __syncthreads();
    m = sm_max[0];
#pragma unroll
    for (int i = 1; i < 8; i++) m = fmaxf(m, sm_max[i]);

    float lsum = (tid == 0) ? __expf(sink - m) : 0.0f;
#pragma unroll
    for (int i = tid; i < SQ / 4; i += 256) {
        float4 v = row4[i];
        float e0 = __expf(v.x * inv - m), e1 = __expf(v.y * inv - m);
        float e2 = __expf(v.z * inv - m), e3 = __expf(v.w * inv - m);
        erow2[2 * i]     = __nv_bfloat162(__float2bfloat16(e0), __float2bfloat16(e1));
        erow2[2 * i + 1] = __nv_bfloat162(__float2bfloat16(e2), __float2bfloat16(e3));
        lsum += (e0 + e1) + (e2 + e3);
    }
#pragma unroll
    for (int o = 16; o; o >>= 1) lsum += __shfl_xor_sync(0xffffffffu, lsum, o);
    if ((tid & 31) == 0) sm_sum[tid >> 5] = lsum;
    __syncthreads();
    if (tid == 0) {
        float t = 0.0f;
#pragma unroll
        for (int i = 0; i < 8; i++) t += sm_sum[i];
        den[s] = t;
    }
}

// ============================================================
extern "C" void kernel_launch(void* const* d_in, const int* in_sizes, int n_in,
                              void* d_out, int out_size) {
    const float* q  = (const float*)d_in[0];
    const float* k  = (const float*)d_in[1];
    const float* v  = (const float*)d_in[2];
    const float* Wq = (const float*)d_in[3];
    const float* bq = (const float*)d_in[4];
    const float* Wk = (const float*)d_in[5];
    const float* bk = (const float*)d_in[6];
    const float* Wv = (const float*)d_in[7];
    const float* bv = (const float*)d_in[8];
    const float* Wo = (const float*)d_in[9];
    const float* bo = (const float*)d_in[10];
    float* out = (float*)d_out;

    float *qq, *kk, *vv, *qk, *qv, *qatt, *den, *scores, *res;
    __nv_bfloat16 *qqb, *kkb, *vvT, *ebf;
    cudaGetSymbolAddress((void**)&qq, g_qq);
    cudaGetSymbolAddress((void**)&kk, g_kk);
    cudaGetSymbolAddress((void**)&vv, g_vv);
    cudaGetSymbolAddress((void**)&qk, g_qk);
    cudaGetSymbolAddress((void**)&qv, g_qv);
    cudaGetSymbolAddress((void**)&qatt, g_qatt);
    cudaGetSymbolAddress((void**)&den, g_den);
    cudaGetSymbolAddress((void**)&scores, g_scores);
    cudaGetSymbolAddress((void**)&res, g_res);
    cudaGetSymbolAddress((void**)&qqb, g_qqb);
    cudaGetSymbolAddress((void**)&kkb, g_kkb);
    cudaGetSymbolAddress((void**)&vvT, g_vvT);
    cudaGetSymbolAddress((void**)&ebf, g_ebf);

    // 5 fused projections (tf32 tensor) + free bf16 copies
    ProjArgs pa;
    pa.t[0] = { q, Wq, bq, qq, qqb, 1, 1 };
    pa.t[1] = { k, Wk, bk, kk, kkb, 1, 1 };
    pa.t[2] = { v, Wv, bv, vv, vvT, 1, 2 };
    pa.t[3] = { q, Wk, bk, qk, nullptr, 0, 0 };
    pa.t[4] = { q, Wv, bv, qv, nullptr, 0, 0 };
    tf32_proj<<<dim3(FD / 64, SQ / 128, 5), 256>>>(pa);

    // q_att diag term (fp32)
    qatt_kernel<<<SQ / 8, 256>>>(qq, qk, qatt);

    // scores = qq @ kk^T  (bf16 HMMA, fp32 accum)
    bf16_gemm_nt<0><<<dim3(SQ / 128, SQ / 128), 256>>>(
        qqb, kkb, scores, FD, SQ, nullptr, nullptr, nullptr);

    // softmax w/ sink: bf16 un-normalized exp + fp32 denom
    softmax_kernel<<<SQ, 256>>>(scores, ebf, qatt, den);

    // res = (E @ vv)/den + qv*qatt  (bf16 HMMA; E K-major, vvT K-major)
    bf16_gemm_nt<1><<<dim3(FD / 128, SQ / 128), 256>>>(
        ebf, vvT, res, SQ, FD, qv, qatt, den);

    // y = relu(res @ Wo^T + bo)  (tf32 tensor)
    ProjArgs po;
    po.t[0] = { res, Wo, bo, out, nullptr, 1, 0 };
    po.t[1] = po.t[0]; po.t[2] = po.t[0]; po.t[3] = po.t[0]; po.t[4] = po.t[0];
    tf32_proj<<<dim3(FD / 64, SQ / 128, 1), 256>>>(po);
}

// round 8
// speedup vs baseline: 5.3669x; 1.1341x over previous
#include <cuda_runtime.h>
#include <cuda_bf16.h>
#include <math.h>
#include <cstdint>

#define SQ 4096
#define FD 512

// ---- scratch (allocation-free: __device__ globals) ----
__device__ float g_qq[SQ * FD];
__device__ float g_kk[SQ * FD];
__device__ float g_vv[SQ * FD];
__device__ float g_qk[SQ * FD];
__device__ float g_qv[SQ * FD];
__device__ float g_res[SQ * FD];
__device__ float g_qatt[SQ];
__device__ float g_den[SQ];
__device__ float g_scores[(size_t)SQ * SQ];          // fp32 raw scores (64MB)
__device__ __nv_bfloat16 g_ebf[(size_t)SQ * SQ];     // bf16 un-normalized exp (32MB)
__device__ __nv_bfloat16 g_qqb[SQ * FD];
__device__ __nv_bfloat16 g_kkb[SQ * FD];
__device__ __nv_bfloat16 g_vvT[FD * SQ];             // vv transposed, K-major

// ================= helpers =================
__device__ __forceinline__ uint32_t smem_u32(const void* p) {
    uint32_t a;
    asm("{ .reg .u64 t; cvta.to.shared.u64 t, %1; cvt.u32.u64 %0, t; }" : "=r"(a) : "l"(p));
    return a;
}
__device__ __forceinline__ void ldsm4(uint32_t* r, uint32_t a) {
    asm volatile("ldmatrix.sync.aligned.m8n8.x4.shared.b16 {%0,%1,%2,%3}, [%4];"
                 : "=r"(r[0]), "=r"(r[1]), "=r"(r[2]), "=r"(r[3]) : "r"(a));
}
__device__ __forceinline__ void mma16816(float* c, const uint32_t* a, uint32_t b0, uint32_t b1) {
    asm volatile("mma.sync.aligned.m16n8k16.row.col.f32.bf16.bf16.f32 "
                 "{%0,%1,%2,%3}, {%4,%5,%6,%7}, {%8,%9}, {%0,%1,%2,%3};"
                 : "+f"(c[0]), "+f"(c[1]), "+f"(c[2]), "+f"(c[3])
                 : "r"(a[0]), "r"(a[1]), "r"(a[2]), "r"(a[3]), "r"(b0), "r"(b1));
}
__device__ __forceinline__ void mma1688(float* c, const uint32_t* a, uint32_t b0, uint32_t b1) {
    asm volatile("mma.sync.aligned.m16n8k8.row.col.f32.tf32.tf32.f32 "
                 "{%0,%1,%2,%3}, {%4,%5,%6,%7}, {%8,%9}, {%0,%1,%2,%3};"
                 : "+f"(c[0]), "+f"(c[1]), "+f"(c[2]), "+f"(c[3])
                 : "r"(a[0]), "r"(a[1]), "r"(a[2]), "r"(a[3]), "r"(b0), "r"(b1));
}
__device__ __forceinline__ uint32_t f2tf(float f) {
    uint32_t r;
    asm("cvt.rna.tf32.f32 %0, %1;" : "=r"(r) : "f"(f));
    return r;
}
__device__ __forceinline__ void cp16(uint32_t s, const void* g) {
    asm volatile("cp.async.cg.shared.global [%0], [%1], 16;" :: "r"(s), "l"(g));
}
#define CP_COMMIT() asm volatile("cp.async.commit_group;" ::: "memory")
#define CP_WAIT0()  asm volatile("cp.async.wait_group 0;" ::: "memory")
#define CP_WAIT1()  asm volatile("cp.async.wait_group 1;" ::: "memory")

// ============================================================
// bf16 NT GEMM via mma.sync m16n8k16 + cp.async 3-stage pipeline:
//   C[M,*] = A[M,K](row,K-contig) @ B[N,K](row,K-contig)^T
// BM=128, BN=128, BK=32, 256 threads (8 warps: 4m x 2n, warp tile 32x64).
// Dynamic smem: 3 stages x (128+128) rows x 80B = 61440 B.
// EPI 0: store fp32.  EPI 1: C = acc/den[r] + qv*qatt (res epilogue).
// ============================================================
template <int EPI>
__global__ void __launch_bounds__(256)
bf16_gemm_nt(const __nv_bfloat16* __restrict__ A, const __nv_bfloat16* __restrict__ B,
             float* __restrict__ C, int K, int ldc,
             const float* __restrict__ qv, const float* __restrict__ qatt,
             const float* __restrict__ den) {
    constexpr int BN = 128, G = BN / 32;
    constexpr int SAS = 40;                 // bf16 per smem row (32 + 8 pad) = 80B
    constexpr int STAGE_A = 128 * SAS * 2;  // 10240 B
    constexpr int STAGE_B = BN * SAS * 2;   // 10240 B
    extern __shared__ char dsm[];
    const uint32_t baseA = smem_u32(dsm);
    const uint32_t baseB = baseA + 3 * STAGE_A;

    const int tid = threadIdx.x, lane = tid & 31, wid = tid >> 5;
    const int wm = wid & 3, wn = wid >> 2;
    const int m0 = blockIdx.y * 128, n0 = blockIdx.x * BN;

    const int cr = tid >> 2;            // staging row
    const int cc = (tid & 3) * 8;       // staging col (bf16 elems), 16B chunks

    const int n = K >> 5;

    auto issue = [&](int chunk) {
        const int s = chunk % 3;
        const int k0 = chunk << 5;
        const uint32_t sa = baseA + s * STAGE_A;
        const uint32_t sb = baseB + s * STAGE_B;
        cp16(sa + cr * 80 + cc * 2, A + (size_t)(m0 + cr) * K + k0 + cc);
        cp16(sa + (cr + 64) * 80 + cc * 2, A + (size_t)(m0 + cr + 64) * K + k0 + cc);
        cp16(sb + cr * 80 + cc * 2, B + (size_t)(n0 + cr) * K + k0 + cc);
        cp16(sb + (cr + 64) * 80 + cc * 2, B + (size_t)(n0 + cr + 64) * K + k0 + cc);
        CP_COMMIT();
    };

    issue(0);
    issue(1);

    const int rowA = lane & 15, koffA = (lane >> 4) * 8;
    const int noffB = (lane & 7) + ((lane >> 4) << 3), koffB = ((lane >> 3) & 1) * 8;

    float c[2][2 * G][4] = {};

    for (int it = 0; it < n; it++) {
        if (it + 1 < n) { CP_WAIT1(); } else { CP_WAIT0(); }
        __syncthreads();
        if (it + 2 < n) issue(it + 2);
        const uint32_t smA = baseA + (it % 3) * STAGE_A;
        const uint32_t smB = baseB + (it % 3) * STAGE_B;
#pragma unroll
        for (int ks = 0; ks < 2; ks++) {
            uint32_t a[2][4], b[G][4];
#pragma unroll
            for (int fm = 0; fm < 2; fm++)
                ldsm4(a[fm], smA + (uint32_t)(((wm * 32 + fm * 16 + rowA) * SAS + ks * 16 + koffA) * 2));
#pragma unroll
            for (int g = 0; g < G; g++)
                ldsm4(b[g], smB + (uint32_t)(((wn * 64 + g * 16 + noffB) * SAS + ks * 16 + koffB) * 2));
#pragma unroll
            for (int fm = 0; fm < 2; fm++)
#pragma unroll
                for (int g = 0; g < G; g++) {
                    mma16816(c[fm][2 * g], a[fm], b[g][0], b[g][1]);
                    mma16816(c[fm][2 * g + 1], a[fm], b[g][2], b[g][3]);
                }
        }
    }

    // ---- epilogue ----
    const int rbase = m0 + wm * 32 + (lane >> 2);
    const int cbase = n0 + wn * 64 + (lane & 3) * 2;
#pragma unroll
    for (int fm = 0; fm < 2; fm++) {
        const int r = rbase + fm * 16;
        if (EPI == 0) {
#pragma unroll
            for (int j = 0; j < 2 * G; j++) {
                const int col = cbase + j * 8;
                *(float2*)(C + (size_t)r * ldc + col) = make_float2(c[fm][j][0], c[fm][j][1]);
                *(float2*)(C + (size_t)(r + 8) * ldc + col) = make_float2(c[fm][j][2], c[fm][j][3]);
            }
        } else {
            const float i0 = __frcp_rn(den[r]),     qa0 = qatt[r];
            const float i1 = __frcp_rn(den[r + 8]), qa1 = qatt[r + 8];
#pragma unroll
            for (int j = 0; j < 2 * G; j++) {
                const int col = cbase + j * 8;
                float2 v0 = *(const float2*)(qv + (size_t)r * ldc + col);
                float2 v1 = *(const float2*)(qv + (size_t)(r + 8) * ldc + col);
                *(float2*)(C + (size_t)r * ldc + col) =
                    make_float2(c[fm][j][0] * i0 + v0.x * qa0, c[fm][j][1] * i0 + v0.y * qa0);
                *(float2*)(C + (size_t)(r + 8) * ldc + col) =
                    make_float2(c[fm][j][2] * i1 + v1.x * qa1, c[fm][j][3] * i1 + v1.y * qa1);
            }
        }
    }
}

// ============================================================
// tf32 NT GEMM (projections), z-fused: per-z {A,B,bias,C,Cb,relu,bf}
// BM=128, BN=64, BK=32, 256 threads, 2-stage smem double buffer,
// reg-staged loads + rna tf32 cvt, one __syncthreads per 32-K chunk.
// Dynamic smem: 2*(128+64)*36 words = 55296 B.
// ============================================================
struct ProjTab {
    const float* A; const float* B; const float* bias;
    float* C; __nv_bfloat16* Cb; int relu; int bf;
};
struct ProjArgs { ProjTab t[5]; };

__global__ void __launch_bounds__(256)
tf32_proj(ProjArgs pa) {
    const ProjTab T = pa.t[blockIdx.z];
    const float* __restrict__ A = T.A;
    const float* __restrict__ B = T.B;
    const int K = FD, N = FD;
    constexpr int SAS = 36;                 // fp32 per smem row (32 + 4 pad) = 144B
    constexpr int STA = 128 * SAS;          // words per A stage
    constexpr int STB = 64 * SAS;
    extern __shared__ uint32_t smw[];
    uint32_t* sA = smw;                     // [2][STA]
    uint32_t* sB = smw + 2 * STA;           // [2][STB]

    const int tid = threadIdx.x, lane = tid & 31, wid = tid >> 5;
    const int wm = wid & 3, wn = wid >> 2;
    const int m0 = blockIdx.y * 128, n0 = blockIdx.x * 64;

    // staging: A 128x32 = 1024 float4-chunks -> 4/thread; B 64x32 -> 2/thread
    int arow[4], acol[4], brow[2], bcol[2];
#pragma unroll
    for (int i = 0; i < 4; i++) {
        const int id = tid + i * 256;
        arow[i] = id >> 3; acol[i] = (id & 7) * 4;
    }
#pragma unroll
    for (int i = 0; i < 2; i++) {
        const int id = tid + i * 256;
        brow[i] = id >> 3; bcol[i] = (id & 7) * 4;
    }

    const int t4 = lane >> 2, c4 = lane & 3;
    float c[2][4][4] = {};

    float4 ra[4], rb[2];
#pragma unroll
    for (int i = 0; i < 4; i++)
        ra[i] = *(const float4*)(A + (size_t)(m0 + arow[i]) * K + acol[i]);
#pragma unroll
    for (int i = 0; i < 2; i++)
        rb[i] = *(const float4*)(B + (size_t)(n0 + brow[i]) * K + bcol[i]);

    auto store_stage = [&](int s) {
        uint32_t* dA = sA + s * STA;
        uint32_t* dB = sB + s * STB;
#pragma unroll
        for (int i = 0; i < 4; i++) {
            uint4 u;
            u.x = f2tf(ra[i].x); u.y = f2tf(ra[i].y); u.z = f2tf(ra[i].z); u.w = f2tf(ra[i].w);
            *(uint4*)&dA[arow[i] * SAS + acol[i]] = u;
        }
#pragma unroll
        for (int i = 0; i < 2; i++) {
            uint4 u;
            u.x = f2tf(rb[i].x); u.y = f2tf(rb[i].y); u.z = f2tf(rb[i].z); u.w = f2tf(rb[i].w);
            *(uint4*)&dB[brow[i] * SAS + bcol[i]] = u;
        }
    };

    const int n = K >> 5;  // 16
    store_stage(0);
    __syncthreads();

    for (int it = 0; it < n; it++) {
        if (it + 1 < n) {
            const int k0 = (it + 1) << 5;
#pragma unroll
            for (int i = 0; i < 4; i++)
                ra[i] = *(const float4*)(A + (size_t)(m0 + arow[i]) * K + k0 + acol[i]);
#pragma unroll
            for (int i = 0; i < 2; i++)
                rb[i] = *(const float4*)(B + (size_t)(n0 + brow[i]) * K + k0 + bcol[i]);
        }
        const uint32_t* cA = sA + (it & 1) * STA;
        const uint32_t* cB = sB + (it & 1) * STB;
#pragma unroll
        for (int ks = 0; ks < 4; ks++) {
            uint32_t a[2][4], b[4][2];
#pragma unroll
            for (int fm = 0; fm < 2; fm++) {
                const int rbx = (wm * 32 + fm * 16 + t4) * SAS + ks * 8 + c4;
                a[fm][0] = cA[rbx];
                a[fm][1] = cA[rbx + 8 * SAS];
                a[fm][2] = cA[rbx + 4];
                a[fm][3] = cA[rbx + 8 * SAS + 4];
            }
#pragma unroll
            for (int nf = 0; nf < 4; nf++) {
                const int nb = (wn * 32 + nf * 8 + t4) * SAS + ks * 8 + c4;
                b[nf][0] = cB[nb];
                b[nf][1] = cB[nb + 4];
            }
#pragma unroll
            for (int fm = 0; fm < 2; fm++)
#pragma unroll
                for (int nf = 0; nf < 4; nf++)
                    mma1688(c[fm][nf], a[fm], b[nf][0], b[nf][1]);
        }
        if (it + 1 < n) {
            store_stage((it + 1) & 1);
            __syncthreads();
        }
    }

    // ---- epilogue ----
    const int rbase = m0 + wm * 32 + t4;
    const int cbase = n0 + wn * 32 + c4 * 2;
    const int relu = T.relu, bf = T.bf;
    float* C = T.C;
    __nv_bfloat16* Cb = T.Cb;
#pragma unroll
    for (int fm = 0; fm < 2; fm++) {
#pragma unroll
        for (int j = 0; j < 4; j++) {
            const int col = cbase + j * 8;
            const float b0 = T.bias[col], b1 = T.bias[col + 1];
#pragma unroll
            for (int h = 0; h < 2; h++) {
                const int r = rbase + fm * 16 + h * 8;
                float v0 = c[fm][j][2 * h] + b0;
                float v1 = c[fm][j][2 * h + 1] + b1;
                if (relu) { v0 = fmaxf(v0, 0.0f); v1 = fmaxf(v1, 0.0f); }
                *(float2*)(C + (size_t)r * N + col) = make_float2(v0, v1);
                if (bf == 1) {
                    *(__nv_bfloat162*)(Cb + (size_t)r * N + col) =
                        __nv_bfloat162(__float2bfloat16(v0), __float2bfloat16(v1));
                } else if (bf == 2) {
                    Cb[(size_t)col * SQ + r] = __float2bfloat16(v0);
                    Cb[(size_t)(col + 1) * SQ + r] = __float2bfloat16(v1);
                }
            }
        }
    }
}

// ============================================================
// q_att[s] = sum_f qq[s,f]*qk[s,f]
// ============================================================
__global__ void qatt_kernel(const float* __restrict__ qq, const float* __restrict__ qk,
                            float* __restrict__ qatt) {
    const int warp = (blockIdx.x * blockDim.x + threadIdx.x) >> 5;
    const int lane = threadIdx.x & 31;
    if (warp >= SQ) return;
    const float4* a = (const float4*)(qq + (size_t)warp * FD);
    const float4* b = (const float4*)(qk + (size_t)warp * FD);
    float sum = 0.0f;
#pragma unroll
    for (int i = lane; i < FD / 4; i += 32) {
        float4 x = a[i], y = b[i];
        sum = fmaf(x.x, y.x, sum); sum = fmaf(x.y, y.y, sum);
        sum = fmaf(x.z, y.z, sum); sum = fmaf(x.w, y.w, sum);
    }
#pragma unroll
    for (int o = 16; o; o >>= 1) sum += __shfl_xor_sync(0xffffffffu, sum, o);
    if (lane == 0) qatt[warp] = sum;
}

// ============================================================
// Row softmax with sink logit; fp32 scores -> bf16 un-normalized exp + fp32 denom
// ============================================================
__global__ void softmax_kernel(const float* __restrict__ scores, __nv_bfloat16* __restrict__ ebf,
                               const float* __restrict__ qatt, float* __restrict__ den) {
    const int s = blockIdx.x;
    const int tid = threadIdx.x;  // 256
    const float inv = rsqrtf(513.0f);
    const float4* row4 = (const float4*)(scores + (size_t)s * SQ);
    __nv_bfloat162* erow2 = (__nv_bfloat162*)(ebf + (size_t)s * SQ);
    const float sink = qatt[s] * inv;

    __shared__ float sm_max[8];
    __shared__ float sm_sum[8];

    float m = sink;
#pragma unroll
    for (int i = tid; i < SQ / 4; i += 256) {
        float4 v = row4[i];
        m = fmaxf(m, fmaxf(fmaxf(v.x, v.y), fmaxf(v.z, v.w)) * inv);
    }
#pragma unroll
    for (int o = 16; o; o >>= 1) m = fmaxf(m, __shfl_xor_sync(0xffffffffu, m, o));
    if ((tid & 31) == 0) sm_max[tid >> 5] = m;
    __syncthreads();
    m = sm_max[0];
#pragma unroll
    for (int i = 1; i < 8; i++) m = fmaxf(m, sm_max[i]);

    float lsum = (tid == 0) ? __expf(sink - m) : 0.0f;
#pragma unroll
    for (int i = tid; i < SQ / 4; i += 256) {
        float4 v = row4[i];
        float e0 = __expf(v.x * inv - m), e1 = __expf(v.y * inv - m);
        float e2 = __expf(v.z * inv - m), e3 = __expf(v.w * inv - m);
        erow2[2 * i]     = __nv_bfloat162(__float2bfloat16(e0), __float2bfloat16(e1));
        erow2[2 * i + 1] = __nv_bfloat162(__float2bfloat16(e2), __float2bfloat16(e3));
        lsum += (e0 + e1) + (e2 + e3);
    }
#pragma unroll
    for (int o = 16; o; o >>= 1) lsum += __shfl_xor_sync(0xffffffffu, lsum, o);
    if ((tid & 31) == 0) sm_sum[tid >> 5] = lsum;
    __syncthreads();
    if (tid == 0) {
        float t = 0.0f;
#pragma unroll
        for (int i = 0; i < 8; i++) t += sm_sum[i];
        den[s] = t;
    }
}

// ============================================================
extern "C" void kernel_launch(void* const* d_in, const int* in_sizes, int n_in,
                              void* d_out, int out_size) {
    const float* q  = (const float*)d_in[0];
    const float* k  = (const float*)d_in[1];
    const float* v  = (const float*)d_in[2];
    const float* Wq = (const float*)d_in[3];
    const float* bq = (const float*)d_in[4];
    const float* Wk = (const float*)d_in[5];
    const float* bk = (const float*)d_in[6];
    const float* Wv = (const float*)d_in[7];
    const float* bv = (const float*)d_in[8];
    const float* Wo = (const float*)d_in[9];
    const float* bo = (const float*)d_in[10];
    float* out = (float*)d_out;

    float *qq, *kk, *vv, *qk, *qv, *qatt, *den, *scores, *res;
    __nv_bfloat16 *qqb, *kkb, *vvT, *ebf;
    cudaGetSymbolAddress((void**)&qq, g_qq);
    cudaGetSymbolAddress((void**)&kk, g_kk);
    cudaGetSymbolAddress((void**)&vv, g_vv);
    cudaGetSymbolAddress((void**)&qk, g_qk);
    cudaGetSymbolAddress((void**)&qv, g_qv);
    cudaGetSymbolAddress((void**)&qatt, g_qatt);
    cudaGetSymbolAddress((void**)&den, g_den);
    cudaGetSymbolAddress((void**)&scores, g_scores);
    cudaGetSymbolAddress((void**)&res, g_res);
    cudaGetSymbolAddress((void**)&qqb, g_qqb);
    cudaGetSymbolAddress((void**)&kkb, g_kkb);
    cudaGetSymbolAddress((void**)&vvT, g_vvT);
    cudaGetSymbolAddress((void**)&ebf, g_ebf);

    const int bfSmem = 3 * (10240 + 10240);   // 61440
    const int pjSmem = 2 * (128 * 36 + 64 * 36) * 4;  // 55296
    cudaFuncSetAttribute(bf16_gemm_nt<0>, cudaFuncAttributeMaxDynamicSharedMemorySize, bfSmem);
    cudaFuncSetAttribute(bf16_gemm_nt<1>, cudaFuncAttributeMaxDynamicSharedMemorySize, bfSmem);
    cudaFuncSetAttribute(tf32_proj, cudaFuncAttributeMaxDynamicSharedMemorySize, pjSmem);

    // 5 fused projections (tf32 tensor) + free bf16 copies
    ProjArgs pa;
    pa.t[0] = { q, Wq, bq, qq, qqb, 1, 1 };
    pa.t[1] = { k, Wk, bk, kk, kkb, 1, 1 };
    pa.t[2] = { v, Wv, bv, vv, vvT, 1, 2 };
    pa.t[3] = { q, Wk, bk, qk, nullptr, 0, 0 };
    pa.t[4] = { q, Wv, bv, qv, nullptr, 0, 0 };
    tf32_proj<<<dim3(FD / 64, SQ / 128, 5), 256, pjSmem>>>(pa);

    // q_att diag term (fp32)
    qatt_kernel<<<SQ / 8, 256>>>(qq, qk, qatt);

    // scores = qq @ kk^T  (bf16 HMMA, fp32 accum)
    bf16_gemm_nt<0><<<dim3(SQ / 128, SQ / 128), 256, bfSmem>>>(
        qqb, kkb, scores, FD, SQ, nullptr, nullptr, nullptr);

    // softmax w/ sink: bf16 un-normalized exp + fp32 denom
    softmax_kernel<<<SQ, 256>>>(scores, ebf, qatt, den);

    // res = (E @ vv)/den + qv*qatt  (bf16 HMMA; E K-major, vvT K-major)
    bf16_gemm_nt<1><<<dim3(FD / 128, SQ / 128), 256, bfSmem>>>(
        ebf, vvT, res, SQ, FD, qv, qatt, den);

    // y = relu(res @ Wo^T + bo)  (tf32 tensor)
    ProjArgs po;
    po.t[0] = { res, Wo, bo, out, nullptr, 1, 0 };
    po.t[1] = po.t[0]; po.t[2] = po.t[0]; po.t[3] = po.t[0]; po.t[4] = po.t[0];
    tf32_proj<<<dim3(FD / 64, SQ / 128, 1), 256, pjSmem>>>(po);
}

// round 9
// speedup vs baseline: 6.8962x; 1.2850x over previous
#include <cuda_runtime.h>
#include <cuda_fp16.h>
#include <math.h>
#include <cstdint>

#define SQ 4096
#define FD 512

// ---- scratch (allocation-free: __device__ globals) ----
__device__ float g_qq[SQ * FD];      // fp32 qq (for qatt)
__device__ float g_qk[SQ * FD];      // fp32 q@Wk^T+bk (for qatt)
__device__ float g_qv[SQ * FD];      // fp32 q@Wv^T+bv (res epilogue)
__device__ float g_qatt[SQ];
__device__ float g_den[SQ];
__device__ __half g_qh[SQ * FD];     // fp16 inputs
__device__ __half g_kh[SQ * FD];
__device__ __half g_vh[SQ * FD];
__device__ __half g_Wqh[FD * FD];    // fp16 weights
__device__ __half g_Wkh[FD * FD];
__device__ __half g_Wvh[FD * FD];
__device__ __half g_Woh[FD * FD];
__device__ __half g_qqh[SQ * FD];    // fp16 relu'd projections
__device__ __half g_kkh[SQ * FD];
__device__ __half g_vvT[FD * SQ];    // vv transposed, K-major
__device__ __half g_resh[SQ * FD];   // fp16 res (A of out-proj)
__device__ __half g_scoresh[(size_t)SQ * SQ];  // fp16 raw scores (32MB)
__device__ __half g_ebf[(size_t)SQ * SQ];      // fp16 un-normalized exp (32MB)

// ================= helpers =================
__device__ __forceinline__ uint32_t smem_u32(const void* p) {
    uint32_t a;
    asm("{ .reg .u64 t; cvta.to.shared.u64 t, %1; cvt.u32.u64 %0, t; }" : "=r"(a) : "l"(p));
    return a;
}
__device__ __forceinline__ void ldsm4(uint32_t* r, uint32_t a) {
    asm volatile("ldmatrix.sync.aligned.m8n8.x4.shared.b16 {%0,%1,%2,%3}, [%4];"
                 : "=r"(r[0]), "=r"(r[1]), "=r"(r[2]), "=r"(r[3]) : "r"(a));
}
__device__ __forceinline__ void mma16816(float* c, const uint32_t* a, uint32_t b0, uint32_t b1) {
    asm volatile("mma.sync.aligned.m16n8k16.row.col.f32.f16.f16.f32 "
                 "{%0,%1,%2,%3}, {%4,%5,%6,%7}, {%8,%9}, {%0,%1,%2,%3};"
                 : "+f"(c[0]), "+f"(c[1]), "+f"(c[2]), "+f"(c[3])
                 : "r"(a[0]), "r"(a[1]), "r"(a[2]), "r"(a[3]), "r"(b0), "r"(b1));
}
__device__ __forceinline__ void cp16(uint32_t s, const void* g) {
    asm volatile("cp.async.cg.shared.global [%0], [%1], 16;" :: "r"(s), "l"(g));
}
#define CP_COMMIT() asm volatile("cp.async.commit_group;" ::: "memory")
#define CP_WAIT0()  asm volatile("cp.async.wait_group 0;" ::: "memory")
#define CP_WAIT1()  asm volatile("cp.async.wait_group 1;" ::: "memory")

// smem geometry shared by all fp16 GEMMs: row = 32 halfs + 8 pad = 80B
#define SAS 40
#define STAGE_BYTES (128 * SAS * 2)   // 10240 per operand stage

// mainloop fragment offsets
#define FRAG_SETUP() \
    const int rowA = lane & 15, koffA = (lane >> 4) * 8; \
    const int noffB = (lane & 7) + ((lane >> 4) << 3), koffB = ((lane >> 3) & 1) * 8;

#define MAINLOOP_BODY(smA, smB) \
    _Pragma("unroll") \
    for (int ks = 0; ks < 2; ks++) { \
        uint32_t a[2][4], b[4][4]; \
        _Pragma("unroll") \
        for (int fm = 0; fm < 2; fm++) \
            ldsm4(a[fm], (smA) + (uint32_t)(((wm * 32 + fm * 16 + rowA) * SAS + ks * 16 + koffA) * 2)); \
        _Pragma("unroll") \
        for (int g = 0; g < 4; g++) \
            ldsm4(b[g], (smB) + (uint32_t)(((wn * 64 + g * 16 + noffB) * SAS + ks * 16 + koffB) * 2)); \
        _Pragma("unroll") \
        for (int fm = 0; fm < 2; fm++) \
            _Pragma("unroll") \
            for (int g = 0; g < 4; g++) { \
                mma16816(c[fm][2 * g], a[fm], b[g][0], b[g][1]); \
                mma16816(c[fm][2 * g + 1], a[fm], b[g][2], b[g][3]); \
            } \
    }

// ============================================================
// fp16 NT GEMM (attention): C = A[M,K] @ B[N,K]^T, fp32 accum.
// BM=BN=128, BK=32, 256 thr (8 warps 4m x 2n), 3-stage cp.async.
// EPI 0: store raw fp16 scores.
// EPI 1: resh = acc/den[r] + qv*qatt (fp16 store).
// ============================================================
template <int EPI>
__global__ void __launch_bounds__(256)
h_gemm_nt(const __half* __restrict__ A, const __half* __restrict__ B,
          __half* __restrict__ O, int K, int ldc,
          const float* __restrict__ qv, const float* __restrict__ qatt,
          const float* __restrict__ den) {
    extern __shared__ char dsm[];
    const uint32_t baseA = smem_u32(dsm);
    const uint32_t baseB = baseA + 3 * STAGE_BYTES;

    const int tid = threadIdx.x, lane = tid & 31, wid = tid >> 5;
    const int wm = wid & 3, wn = wid >> 2;
    const int m0 = blockIdx.y * 128, n0 = blockIdx.x * 128;

    const int cr = tid >> 2;
    const int cc = (tid & 3) * 8;
    const int n = K >> 5;

    auto issue = [&](int chunk) {
        const int s = chunk % 3;
        const int k0 = chunk << 5;
        const uint32_t sa = baseA + s * STAGE_BYTES;
        const uint32_t sb = baseB + s * STAGE_BYTES;
        cp16(sa + cr * 80 + cc * 2, A + (size_t)(m0 + cr) * K + k0 + cc);
        cp16(sa + (cr + 64) * 80 + cc * 2, A + (size_t)(m0 + cr + 64) * K + k0 + cc);
        cp16(sb + cr * 80 + cc * 2, B + (size_t)(n0 + cr) * K + k0 + cc);
        cp16(sb + (cr + 64) * 80 + cc * 2, B + (size_t)(n0 + cr + 64) * K + k0 + cc);
        CP_COMMIT();
    };

    issue(0);
    issue(1);

    FRAG_SETUP();
    float c[2][8][4] = {};

    for (int it = 0; it < n; it++) {
        if (it + 1 < n) { CP_WAIT1(); } else { CP_WAIT0(); }
        __syncthreads();
        if (it + 2 < n) issue(it + 2);
        const uint32_t smA = baseA + (it % 3) * STAGE_BYTES;
        const uint32_t smB = baseB + (it % 3) * STAGE_BYTES;
        MAINLOOP_BODY(smA, smB);
    }

    // ---- epilogue ----
    const int rbase = m0 + wm * 32 + (lane >> 2);
    const int cbase = n0 + wn * 64 + (lane & 3) * 2;
#pragma unroll
    for (int fm = 0; fm < 2; fm++) {
        const int r = rbase + fm * 16;
        if (EPI == 0) {
#pragma unroll
            for (int j = 0; j < 8; j++) {
                const int col = cbase + j * 8;
                *(__half2*)(O + (size_t)r * ldc + col) = __floats2half2_rn(c[fm][j][0], c[fm][j][1]);
                *(__half2*)(O + (size_t)(r + 8) * ldc + col) = __floats2half2_rn(c[fm][j][2], c[fm][j][3]);
            }
        } else {
            const float i0 = __frcp_rn(den[r]),     qa0 = qatt[r];
            const float i1 = __frcp_rn(den[r + 8]), qa1 = qatt[r + 8];
#pragma unroll
            for (int j = 0; j < 8; j++) {
                const int col = cbase + j * 8;
                float2 v0 = *(const float2*)(qv + (size_t)r * ldc + col);
                float2 v1 = *(const float2*)(qv + (size_t)(r + 8) * ldc + col);
                *(__half2*)(O + (size_t)r * ldc + col) =
                    __floats2half2_rn(c[fm][j][0] * i0 + v0.x * qa0, c[fm][j][1] * i0 + v0.y * qa0);
                *(__half2*)(O + (size_t)(r + 8) * ldc + col) =
                    __floats2half2_rn(c[fm][j][2] * i1 + v1.x * qa1, c[fm][j][3] * i1 + v1.y * qa1);
            }
        }
    }
}

// ============================================================
// fp16 NT GEMM (projections), z-fused table:
//   per-z: Cf?=fp32 out, Ch?=fp16 out (hm 1=row, 2=transposed), bias, relu.
// Same tile/pipeline as h_gemm_nt. K = N = FD.
// ============================================================
struct ProjTab {
    const __half* A; const __half* B; const float* bias;
    float* Cf; __half* Ch; int hm; int relu;
};
struct ProjArgs { ProjTab t[5]; };

__global__ void __launch_bounds__(256)
h_proj(ProjArgs pa) {
    const ProjTab T = pa.t[blockIdx.z];
    const __half* __restrict__ A = T.A;
    const __half* __restrict__ B = T.B;
    const int K = FD, N = FD;
    extern __shared__ char dsm[];
    const uint32_t baseA = smem_u32(dsm);
    const uint32_t baseB = baseA + 3 * STAGE_BYTES;

    const int tid = threadIdx.x, lane = tid & 31, wid = tid >> 5;
    const int wm = wid & 3, wn = wid >> 2;
    const int m0 = blockIdx.y * 128, n0 = blockIdx.x * 128;

    const int cr = tid >> 2;
    const int cc = (tid & 3) * 8;
    const int n = K >> 5;  // 16

    auto issue = [&](int chunk) {
        const int s = chunk % 3;
        const int k0 = chunk << 5;
        const uint32_t sa = baseA + s * STAGE_BYTES;
        const uint32_t sb = baseB + s * STAGE_BYTES;
        cp16(sa + cr * 80 + cc * 2, A + (size_t)(m0 + cr) * K + k0 + cc);
        cp16(sa + (cr + 64) * 80 + cc * 2, A + (size_t)(m0 + cr + 64) * K + k0 + cc);
        cp16(sb + cr * 80 + cc * 2, B + (size_t)(n0 + cr) * K + k0 + cc);
        cp16(sb + (cr + 64) * 80 + cc * 2, B + (size_t)(n0 + cr + 64) * K + k0 + cc);
        CP_COMMIT();
    };

    issue(0);
    issue(1);

    FRAG_SETUP();
    float c[2][8][4] = {};

    for (int it = 0; it < n; it++) {
        if (it + 1 < n) { CP_WAIT1(); } else { CP_WAIT0(); }
        __syncthreads();
        if (it + 2 < n) issue(it + 2);
        const uint32_t smA = baseA + (it % 3) * STAGE_BYTES;
        const uint32_t smB = baseB + (it % 3) * STAGE_BYTES;
        MAINLOOP_BODY(smA, smB);
    }

    // ---- epilogue ----
    const int rbase = m0 + wm * 32 + (lane >> 2);
    const int cbase = n0 + wn * 64 + (lane & 3) * 2;
    float* Cf = T.Cf;
    __half* Ch = T.Ch;
    const int hm = T.hm, relu = T.relu;
#pragma unroll
    for (int fm = 0; fm < 2; fm++) {
#pragma unroll
        for (int j = 0; j < 8; j++) {
            const int col = cbase + j * 8;
            const float b0 = T.bias[col], b1 = T.bias[col + 1];
#pragma unroll
            for (int h = 0; h < 2; h++) {
                const int r = rbase + fm * 16 + h * 8;
                float v0 = c[fm][j][2 * h] + b0;
                float v1 = c[fm][j][2 * h + 1] + b1;
                if (relu) { v0 = fmaxf(v0, 0.0f); v1 = fmaxf(v1, 0.0f); }
                if (Cf) *(float2*)(Cf + (size_t)r * N + col) = make_float2(v0, v1);
                if (hm == 1) {
                    *(__half2*)(Ch + (size_t)r * N + col) = __floats2half2_rn(v0, v1);
                } else if (hm == 2) {
                    Ch[(size_t)col * SQ + r] = __float2half_rn(v0);
                    Ch[(size_t)(col + 1) * SQ + r] = __float2half_rn(v1);
                }
            }
        }
    }
}

// ============================================================
// fp32 -> fp16 conversion, z-segmented
// ============================================================
struct CvtTab { const float* src; __half* dst; int n; };
struct CvtArgs { CvtTab t[7]; };

__global__ void f2h_kernel(CvtArgs a) {
    const CvtTab T = a.t[blockIdx.z];
    const int i = (blockIdx.x * blockDim.x + threadIdx.x) * 4;
    if (i < T.n) {
        float4 v = *(const float4*)(T.src + i);
        __half2 h0 = __floats2half2_rn(v.x, v.y);
        __half2 h1 = __floats2half2_rn(v.z, v.w);
        *(uint2*)(T.dst + i) = make_uint2(*(uint32_t*)&h0, *(uint32_t*)&h1);
    }
}

// ============================================================
// q_att[s] = sum_f qq[s,f]*qk[s,f]   (fp32)
// ============================================================
__global__ void qatt_kernel(const float* __restrict__ qq, const float* __restrict__ qk,
                            float* __restrict__ qatt) {
    const int warp = (blockIdx.x * blockDim.x + threadIdx.x) >> 5;
    const int lane = threadIdx.x & 31;
    if (warp >= SQ) return;
    const float4* a = (const float4*)(qq + (size_t)warp * FD);
    const float4* b = (const float4*)(qk + (size_t)warp * FD);
    float sum = 0.0f;
#pragma unroll
    for (int i = lane; i < FD / 4; i += 32) {
        float4 x = a[i], y = b[i];
        sum = fmaf(x.x, y.x, sum); sum = fmaf(x.y, y.y, sum);
        sum = fmaf(x.z, y.z, sum); sum = fmaf(x.w, y.w, sum);
    }
#pragma unroll
    for (int o = 16; o; o >>= 1) sum += __shfl_xor_sync(0xffffffffu, sum, o);
    if (lane == 0) qatt[warp] = sum;
}

// ============================================================
// Row softmax w/ sink: fp16 scores -> fp16 un-normalized exp + fp32 denom
// ============================================================
__global__ void softmax_kernel(const __half* __restrict__ scores, __half* __restrict__ ebf,
                               const float* __restrict__ qatt, float* __restrict__ den) {
    const int s = blockIdx.x;
    const int tid = threadIdx.x;  // 256
    const float inv = rsqrtf(513.0f);
    const uint4* row8 = (const uint4*)(scores + (size_t)s * SQ);  // 8 halfs per load
    uint4* erow8 = (uint4*)(ebf + (size_t)s * SQ);
    const float sink = qatt[s] * inv;

    __shared__ float sm_max[8];
    __shared__ float sm_sum[8];

    float m = sink;
#pragma unroll
    for (int i = tid; i < SQ / 8; i += 256) {
        uint4 u = row8[i];
        const __half2* h = (const __half2*)&u;
#pragma unroll
        for (int p = 0; p < 4; p++) {
            float2 f = __half22float2(h[p]);
            m = fmaxf(m, fmaxf(f.x, f.y) * inv);
        }
    }
#pragma unroll
    for (int o = 16; o; o >>= 1) m = fmaxf(m, __shfl_xor_sync(0xffffffffu, m, o));
    if ((tid & 31) == 0) sm_max[tid >> 5] = m;
    __syncthreads();
    m = sm_max[0];
#pragma unroll
    for (int i = 1; i < 8; i++) m = fmaxf(m, sm_max[i]);

    float lsum = (tid == 0) ? __expf(sink - m) : 0.0f;
#pragma unroll
    for (int i = tid; i < SQ / 8; i += 256) {
        uint4 u = row8[i];
        const __half2* h = (const __half2*)&u;
        uint4 o;
        __half2* oh = (__half2*)&o;
#pragma unroll
        for (int p = 0; p < 4; p++) {
            float2 f = __half22float2(h[p]);
            float e0 = __expf(f.x * inv - m);
            float e1 = __expf(f.y * inv - m);
            oh[p] = __floats2half2_rn(e0, e1);
            lsum += e0 + e1;
        }
        erow8[i] = o;
    }
#pragma unroll
    for (int o = 16; o; o >>= 1) lsum += __shfl_xor_sync(0xffffffffu, lsum, o);
    if ((tid & 31) == 0) sm_sum[tid >> 5] = lsum;
    __syncthreads();
    if (tid == 0) {
        float t = 0.0f;
#pragma unroll
        for (int i = 0; i < 8; i++) t += sm_sum[i];
        den[s] = t;
    }
}

// ============================================================
// Final projection: reuse h_proj table but writes fp32 out; provided via Cf.
// ============================================================
extern "C" void kernel_launch(void* const* d_in, const int* in_sizes, int n_in,
                              void* d_out, int out_size) {
    const float* q  = (const float*)d_in[0];
    const float* k  = (const float*)d_in[1];
    const float* v  = (const float*)d_in[2];
    const float* Wq = (const float*)d_in[3];
    const float* bq = (const float*)d_in[4];
    const float* Wk = (const float*)d_in[5];
    const float* bk = (const float*)d_in[6];
    const float* Wv = (const float*)d_in[7];
    const float* bv = (const float*)d_in[8];
    const float* Wo = (const float*)d_in[9];
    const float* bo = (const float*)d_in[10];
    float* out = (float*)d_out;

    float *qq, *qk, *qv, *qatt, *den;
    __half *qh, *kh, *vh, *Wqh, *Wkh, *Wvh, *Woh;
    __half *qqh, *kkh, *vvT, *resh, *scoresh, *ebf;
    cudaGetSymbolAddress((void**)&qq, g_qq);
    cudaGetSymbolAddress((void**)&qk, g_qk);
    cudaGetSymbolAddress((void**)&qv, g_qv);
    cudaGetSymbolAddress((void**)&qatt, g_qatt);
    cudaGetSymbolAddress((void**)&den, g_den);
    cudaGetSymbolAddress((void**)&qh, g_qh);
    cudaGetSymbolAddress((void**)&kh, g_kh);
    cudaGetSymbolAddress((void**)&vh, g_vh);
    cudaGetSymbolAddress((void**)&Wqh, g_Wqh);
    cudaGetSymbolAddress((void**)&Wkh, g_Wkh);
    cudaGetSymbolAddress((void**)&Wvh, g_Wvh);
    cudaGetSymbolAddress((void**)&Woh, g_Woh);
    cudaGetSymbolAddress((void**)&qqh, g_qqh);
    cudaGetSymbolAddress((void**)&kkh, g_kkh);
    cudaGetSymbolAddress((void**)&vvT, g_vvT);
    cudaGetSymbolAddress((void**)&resh, g_resh);
    cudaGetSymbolAddress((void**)&scoresh, g_scoresh);
    cudaGetSymbolAddress((void**)&ebf, g_ebf);

    const int gSmem = 6 * STAGE_BYTES;  // 61440
    cudaFuncSetAttribute(h_gemm_nt<0>, cudaFuncAttributeMaxDynamicSharedMemorySize, gSmem);
    cudaFuncSetAttribute(h_gemm_nt<1>, cudaFuncAttributeMaxDynamicSharedMemorySize, gSmem);
    cudaFuncSetAttribute(h_proj, cudaFuncAttributeMaxDynamicSharedMemorySize, gSmem);

    // 1) fp32 -> fp16 conversions (inputs + weights)
    CvtArgs ca;
    ca.t[0] = { q, qh, SQ * FD };
    ca.t[1] = { k, kh, SQ * FD };
    ca.t[2] = { v, vh, SQ * FD };
    ca.t[3] = { Wq, Wqh, FD * FD };
    ca.t[4] = { Wk, Wkh, FD * FD };
    ca.t[5] = { Wv, Wvh, FD * FD };
    ca.t[6] = { Wo, Woh, FD * FD };
    f2h_kernel<<<dim3(SQ * FD / 1024, 1, 7), 256>>>(ca);

    // 2) 5 fused projections (fp16 HMMA)
    ProjArgs pa;
    pa.t[0] = { qh, Wqh, bq, qq,      qqh,     1, 1 };  // qq fp32 + fp16 row
    pa.t[1] = { kh, Wkh, bk, nullptr, kkh,     1, 1 };  // kk fp16 row only
    pa.t[2] = { vh, Wvh, bv, nullptr, vvT,     2, 1 };  // vv fp16 transposed only
    pa.t[3] = { qh, Wkh, bk, qk,      nullptr, 0, 0 };  // q_k fp32
    pa.t[4] = { qh, Wvh, bv, qv,      nullptr, 0, 0 };  // q_v fp32
    h_proj<<<dim3(FD / 128, SQ / 128, 5), 256, gSmem>>>(pa);

    // 3) q_att diag term (fp32)
    qatt_kernel<<<SQ / 8, 256>>>(qq, qk, qatt);

    // 4) scores = qq @ kk^T  (fp16 HMMA, fp32 accum, fp16 store)
    h_gemm_nt<0><<<dim3(SQ / 128, SQ / 128), 256, gSmem>>>(
        qqh, kkh, scoresh, FD, SQ, nullptr, nullptr, nullptr);

    // 5) softmax w/ sink
    softmax_kernel<<<SQ, 256>>>(scoresh, ebf, qatt, den);

    // 6) res = (E @ vv)/den + qv*qatt  -> fp16 resh
    h_gemm_nt<1><<<dim3(FD / 128, SQ / 128), 256, gSmem>>>(
        ebf, vvT, resh, SQ, FD, qv, qatt, den);

    // 7) y = relu(res @ Wo^T + bo)  (fp16 HMMA, fp32 out)
    ProjArgs po;
    po.t[0] = { resh, Woh, bo, out, nullptr, 0, 1 };
    po.t[1] = po.t[0]; po.t[2] = po.t[0]; po.t[3] = po.t[0]; po.t[4] = po.t[0];
    h_proj<<<dim3(FD / 128, SQ / 128, 1), 256, gSmem>>>(po);
}